// round 15
// baseline (speedup 1.0000x reference)
#include <cuda_runtime.h>
#include <cuda_bf16.h>

// SoftHistogram via fine-histogram factorization, SINGLE persistent kernel:
//   out[ch][j] = normalize( sum_t counts[ch][t] * W[t][j] )
// W[t][j] = per-pixel-normalized Gaussian weight at x_t = t/TF (round-binning
// via the 2^23 magic-FMA trick, rows t = 0..TF inclusive).
//
// R13 vs R12 (23.0us; best 19.2us): the two-kernel split paid a full launch +
// 768-block ramp for ~1.4us of real contraction work. Now ONE kernel:
//   blocks [0,TBLK): build W, bump g_wdone.
//   blocks [TBLK,641): per-channel smem histogram -> RED merge -> bump
//     g_hdone[ch] -> spin until channel counts + W ready -> contraction of a
//     128-row slice (transposed acc[4] layout) -> RED to g_hist -> last
//     arriver normalizes + writes out + resets all state for graph replay.
// 641 blocks < 1-wave capacity (~8 blocks/SM) => producers always resident =>
// spins are deadlock-free.

#define TF    2048
#define ROWS  (TF + 1)            // 2049 table rows (bin 0..2048)
#define RPAD  2052                // row pad for g_counts
#define NCH   24                  // 8 * 3 channels
#define BINS  64
#define PPC   (512 * 512)         // pixels per channel
#define HBLK  16                  // hist blocks per channel
#define PXB   (PPC / HBLK)        // 16384 pixels per hist block
#define TBLK  ((ROWS + 7) / 8)    // 257 table blocks (8 rows/block)
#define RSPL  129                 // contraction rows per hist block (16*129>=2049)

__device__ unsigned int g_counts[NCH][RPAD];  // fine histograms (BSS zero)
__device__ float        g_W[ROWS][BINS];      // weight table
__device__ float        g_hist[NCH][BINS];    // contraction accumulators (BSS zero)
__device__ unsigned int g_wdone;              // table blocks completed
__device__ unsigned int g_hdone[NCH];         // hist blocks completed per channel
__device__ unsigned int g_cdone[NCH];         // contraction blocks completed
__device__ unsigned int g_fin;                // channels fully finished

__global__ void __launch_bounds__(256) hx_all(const float* __restrict__ x,
                                              const float* __restrict__ centers,
                                              float* __restrict__ out) {
    __shared__ unsigned int sh[RPAD];
    __shared__ float part[16][BINS + 4];
    const int b   = blockIdx.x;
    const int tid = threadIdx.x;

    // ======================= table blocks =======================
    if (b < TBLK) {
        const int warp = tid >> 5;
        const int lane = tid & 31;
        const int t    = b * 8 + warp;
        if (t < ROWS) {
            const float xt   = (float)t * (1.0f / (float)TF);
            const float invs = 1.0f / (0.02f + 1e-12f);   // reference SIGMA guard
            float z0 = (xt - __ldg(&centers[lane]))      * invs;
            float z1 = (xt - __ldg(&centers[lane + 32])) * invs;
            float e0 = expf(-0.5f * z0 * z0);
            float e1 = expf(-0.5f * z1 * z1);
            float s = e0 + e1;
#pragma unroll
            for (int off = 16; off > 0; off >>= 1)
                s += __shfl_xor_sync(0xffffffffu, s, off);
            const float r = 1.0f / (s + 1e-12f);
            g_W[t][lane]      = e0 * r;
            g_W[t][lane + 32] = e1 * r;
        }
        __threadfence();                 // each thread's W stores device-visible
        __syncthreads();                 // ...before tid0 signals
        if (tid == 0) atomicAdd(&g_wdone, 1u);
        return;
    }

    // ======================= hist blocks =======================
    const int hb  = b - TBLK;
    const int ch  = hb / HBLK;
    const int blk = hb % HBLK;

    for (int i = tid; i < RPAD; i += 256) sh[i] = 0u;
    __syncthreads();

    {
        const float4* __restrict__ p =
            reinterpret_cast<const float4*>(x + (size_t)ch * PPC + (size_t)blk * PXB);
        const float MAGIC = 8388608.0f;   // 2^23
#pragma unroll 4
        for (int i = 0; i < PXB / (256 * 4); i++) {
            float4 v = p[i * 256 + tid];
            unsigned b0 = __float_as_uint(fmaf(v.x, (float)TF, MAGIC)) & 0xFFFu;
            unsigned b1 = __float_as_uint(fmaf(v.y, (float)TF, MAGIC)) & 0xFFFu;
            unsigned b2 = __float_as_uint(fmaf(v.z, (float)TF, MAGIC)) & 0xFFFu;
            unsigned b3 = __float_as_uint(fmaf(v.w, (float)TF, MAGIC)) & 0xFFFu;
            atomicAdd(&sh[b0], 1u);
            atomicAdd(&sh[b1], 1u);
            atomicAdd(&sh[b2], 1u);
            atomicAdd(&sh[b3], 1u);
        }
    }
    __syncthreads();

    {
        unsigned int* __restrict__ gc = g_counts[ch];
        for (int i = tid; i < ROWS; i += 256) {
            unsigned v = sh[i];
            if (v) atomicAdd(&gc[i], v);
        }
    }
    __threadfence();
    __syncthreads();
    if (tid == 0) atomicAdd(&g_hdone[ch], 1u);

    // ---- wait: W table complete AND this channel's counts complete ----
    if (tid == 0) {
        while (*((volatile unsigned int*)&g_wdone) < (unsigned)TBLK) __nanosleep(64);
        while (*((volatile unsigned int*)&g_hdone[ch]) < (unsigned)HBLK) __nanosleep(64);
        __threadfence();
    }
    __syncthreads();

    // ======================= contraction =======================
    // Transposed layout: thread owns bin-group jg (4 bins) and row-slice rs.
    const int jg = tid & 15;
    const int rs = tid >> 4;
    const int r0 = blk * RSPL;
    const int r1 = min(r0 + RSPL, ROWS);

    float ax = 0.f, ay = 0.f, az = 0.f, aw = 0.f;
    const float4* __restrict__ W4 = reinterpret_cast<const float4*>(g_W);
    const unsigned int* __restrict__ gc = g_counts[ch];

    for (int r = r0 + rs; r < r1; r += 16) {
        float  c = (float)__ldcg(&gc[r]);            // L2 load (cross-SM writes)
        float4 w = __ldcg(&W4[r * 16 + jg]);
        ax = fmaf(c, w.x, ax);
        ay = fmaf(c, w.y, ay);
        az = fmaf(c, w.z, az);
        aw = fmaf(c, w.w, aw);
    }

    // all reads of this slice complete before anyone zeroes it (R8 race fix)
    __syncthreads();
    for (int r = r0 + tid; r < r1; r += 256) g_counts[ch][r] = 0u;

    part[rs][jg * 4 + 0] = ax;
    part[rs][jg * 4 + 1] = ay;
    part[rs][jg * 4 + 2] = az;
    part[rs][jg * 4 + 3] = aw;
    __syncthreads();

    if (tid < BINS) {
        float s = 0.0f;
#pragma unroll
        for (int k = 0; k < 16; k++) s += part[k][tid];
        atomicAdd(&g_hist[ch][tid], s);
    }
    __threadfence();
    __syncthreads();

    __shared__ unsigned int s_last;
    if (tid == 0)
        s_last = (atomicAdd(&g_cdone[ch], 1u) == HBLK - 1u) ? 1u : 0u;
    __syncthreads();
    if (!s_last) return;

    // ---- last contraction block for this channel: normalize + reset ----
    const int warp = tid >> 5;
    const int lane = tid & 31;
    __threadfence();

    float m = 0.0f;
    if (tid < BINS)
        m = *((volatile float*)&g_hist[ch][tid]) * (1.0f / (float)PPC);

    float t = (tid < BINS) ? m : 0.0f;
#pragma unroll
    for (int off = 16; off > 0; off >>= 1)
        t += __shfl_xor_sync(0xffffffffu, t, off);

    __shared__ float ws[8];
    if (lane == 0) ws[warp] = t;
    __syncthreads();

    if (tid < BINS) {
        float tot = ws[0] + ws[1];
        out[ch * BINS + tid] = m / (tot + 1e-12f);
        g_hist[ch][tid] = 0.0f;                     // reset for next replay
    }
    if (tid == 0) {
        g_cdone[ch] = 0u;
        g_hdone[ch] = 0u;
        // last channel overall resets the global table counter
        if (atomicAdd(&g_fin, 1u) == NCH - 1u) {
            g_wdone = 0u;
            g_fin   = 0u;
        }
    }
}

// ---------------------------------------------------------------------------
extern "C" void kernel_launch(void* const* d_in, const int* in_sizes, int n_in,
                              void* d_out, int out_size) {
    const float* x       = (const float*)d_in[0];   // (8,3,512,512) fp32
    const float* centers = (const float*)d_in[1];   // (64,) fp32
    float* out           = (float*)d_out;           // (8,3,64) fp32

    hx_all<<<TBLK + HBLK * NCH, 256>>>(x, centers, out);
}

// round 16
// speedup vs baseline: 1.4412x; 1.4412x over previous
#include <cuda_runtime.h>
#include <cuda_bf16.h>

// SoftHistogram via fine-histogram factorization, SINGLE kernel, uniform grid:
//   out[ch][j] = normalize( sum_t counts[ch][t] * W[t][j] )
// W[t][j] = per-pixel-normalized Gaussian weight at x_t = t/TF (round-binning
// via the 2^23 magic-FMA trick, rows t = 0..TF inclusive).
//
// R15 vs R13 (25.1us) / best R11 (19.2us): fused kernel, now with a UNIFORM
// 384-block grid: every block does (1) a W-table slice (one row per warp,
// 3072 warps cover 2049 rows), (2) its channel-slice histogram, (3) after
// device-side flags, a 129-row contraction slice, (4) last arriver per
// channel normalizes + writes + resets all state for graph replay. Smem for
// the contraction combine reuses the histogram buffer (8.2KB total).

#define TF    2048
#define ROWS  (TF + 1)            // 2049 table rows (bin 0..2048)
#define RPAD  2052                // row pad for g_counts / smem
#define NCH   24                  // 8 * 3 channels
#define BINS  64
#define PPC   (512 * 512)         // pixels per channel
#define HBLK  16                  // hist blocks per channel
#define PXB   (PPC / HBLK)        // 16384 pixels per hist block
#define GRID  (NCH * HBLK)        // 384 blocks
#define RSPL  129                 // contraction rows per block (16*129 >= 2049)

__device__ unsigned int g_counts[NCH][RPAD];  // fine histograms (BSS zero)
__device__ float        g_W[ROWS][BINS];      // weight table
__device__ float        g_hist[NCH][BINS];    // contraction accumulators (BSS zero)
__device__ unsigned int g_wdone;              // blocks done with table phase
__device__ unsigned int g_hdone[NCH];         // hist blocks completed per channel
__device__ unsigned int g_cdone[NCH];         // contraction blocks completed
__device__ unsigned int g_fin;                // channels fully finished

__global__ void __launch_bounds__(256) hx_all(const float* __restrict__ x,
                                              const float* __restrict__ centers,
                                              float* __restrict__ out) {
    __shared__ unsigned int sh[RPAD];          // hist counts, then reused as combine
    const int b    = blockIdx.x;               // 0..383
    const int tid  = threadIdx.x;
    const int warp = tid >> 5;
    const int lane = tid & 31;
    const int ch   = b / HBLK;
    const int blk  = b % HBLK;

    // ================= phase 0: W table (one row per warp) =================
    {
        const int t = b * 8 + warp;            // global warp id = row
        if (t < ROWS) {
            const float xt   = (float)t * (1.0f / (float)TF);
            const float invs = 1.0f / (0.02f + 1e-12f);   // reference SIGMA guard
            float z0 = (xt - __ldg(&centers[lane]))      * invs;
            float z1 = (xt - __ldg(&centers[lane + 32])) * invs;
            float e0 = expf(-0.5f * z0 * z0);
            float e1 = expf(-0.5f * z1 * z1);
            float s = e0 + e1;
#pragma unroll
            for (int off = 16; off > 0; off >>= 1)
                s += __shfl_xor_sync(0xffffffffu, s, off);
            const float r = 1.0f / (s + 1e-12f);
            g_W[t][lane]      = e0 * r;
            g_W[t][lane + 32] = e1 * r;
        }
        __threadfence();
        __syncthreads();
        if (tid == 0) atomicAdd(&g_wdone, 1u);
    }

    // ================= phase 1: per-channel-slice histogram =================
    for (int i = tid; i < RPAD; i += 256) sh[i] = 0u;
    __syncthreads();

    {
        const float4* __restrict__ p =
            reinterpret_cast<const float4*>(x + (size_t)ch * PPC + (size_t)blk * PXB);
        const float MAGIC = 8388608.0f;        // 2^23
#pragma unroll 4
        for (int i = 0; i < PXB / (256 * 4); i++) {
            float4 v = p[i * 256 + tid];
            unsigned b0 = __float_as_uint(fmaf(v.x, (float)TF, MAGIC)) & 0xFFFu;
            unsigned b1 = __float_as_uint(fmaf(v.y, (float)TF, MAGIC)) & 0xFFFu;
            unsigned b2 = __float_as_uint(fmaf(v.z, (float)TF, MAGIC)) & 0xFFFu;
            unsigned b3 = __float_as_uint(fmaf(v.w, (float)TF, MAGIC)) & 0xFFFu;
            atomicAdd(&sh[b0], 1u);
            atomicAdd(&sh[b1], 1u);
            atomicAdd(&sh[b2], 1u);
            atomicAdd(&sh[b3], 1u);
        }
    }
    __syncthreads();

    {
        unsigned int* __restrict__ gc = g_counts[ch];
        for (int i = tid; i < ROWS; i += 256) {
            unsigned v = sh[i];
            if (v) atomicAdd(&gc[i], v);
        }
    }
    __threadfence();
    __syncthreads();
    if (tid == 0) atomicAdd(&g_hdone[ch], 1u);

    // ---- wait: W table complete AND this channel's counts complete ----
    if (tid == 0) {
        while (*((volatile unsigned int*)&g_wdone) < (unsigned)GRID) __nanosleep(32);
        while (*((volatile unsigned int*)&g_hdone[ch]) < (unsigned)HBLK) __nanosleep(32);
        __threadfence();
    }
    __syncthreads();

    // ================= phase 2: contraction (transposed layout) =============
    const int jg = tid & 15;                   // bin group (4 bins)
    const int rs = tid >> 4;                   // row slice 0..15
    const int r0 = blk * RSPL;
    const int r1 = min(r0 + RSPL, ROWS);

    float ax = 0.f, ay = 0.f, az = 0.f, aw = 0.f;
    const float4* __restrict__ W4 = reinterpret_cast<const float4*>(g_W);
    const unsigned int* __restrict__ gc = g_counts[ch];

    for (int r = r0 + rs; r < r1; r += 16) {
        float  c = (float)__ldcg(&gc[r]);      // L2 (written by other SMs)
        float4 w = __ldcg(&W4[r * 16 + jg]);
        ax = fmaf(c, w.x, ax);
        ay = fmaf(c, w.y, ay);
        az = fmaf(c, w.z, az);
        aw = fmaf(c, w.w, aw);
    }

    // all reads of this slice complete before anyone zeroes it (R8 race fix)
    __syncthreads();
    for (int r = r0 + tid; r < r1; r += 256) g_counts[ch][r] = 0u;

    float* __restrict__ part = reinterpret_cast<float*>(sh);   // reuse smem
    part[rs * (BINS + 4) + jg * 4 + 0] = ax;
    part[rs * (BINS + 4) + jg * 4 + 1] = ay;
    part[rs * (BINS + 4) + jg * 4 + 2] = az;
    part[rs * (BINS + 4) + jg * 4 + 3] = aw;
    __syncthreads();

    if (tid < BINS) {
        float s = 0.0f;
#pragma unroll
        for (int k = 0; k < 16; k++) s += part[k * (BINS + 4) + tid];
        atomicAdd(&g_hist[ch][tid], s);
    }
    __threadfence();
    __syncthreads();

    __shared__ unsigned int s_last;
    if (tid == 0)
        s_last = (atomicAdd(&g_cdone[ch], 1u) == HBLK - 1u) ? 1u : 0u;
    __syncthreads();
    if (!s_last) return;

    // ======= phase 3: last block per channel — normalize + reset ===========
    __threadfence();

    float m = 0.0f;
    if (tid < BINS)
        m = *((volatile float*)&g_hist[ch][tid]) * (1.0f / (float)PPC);

    float t = (tid < BINS) ? m : 0.0f;
#pragma unroll
    for (int off = 16; off > 0; off >>= 1)
        t += __shfl_xor_sync(0xffffffffu, t, off);

    __shared__ float ws[8];
    if (lane == 0) ws[warp] = t;
    __syncthreads();

    if (tid < BINS) {
        float tot = ws[0] + ws[1];
        out[ch * BINS + tid] = m / (tot + 1e-12f);
        g_hist[ch][tid] = 0.0f;                // reset for next replay
    }
    if (tid == 0) {
        g_cdone[ch] = 0u;
        g_hdone[ch] = 0u;
        if (atomicAdd(&g_fin, 1u) == NCH - 1u) {   // globally last channel
            g_wdone = 0u;
            g_fin   = 0u;
        }
    }
}

// ---------------------------------------------------------------------------
extern "C" void kernel_launch(void* const* d_in, const int* in_sizes, int n_in,
                              void* d_out, int out_size) {
    const float* x       = (const float*)d_in[0];   // (8,3,512,512) fp32
    const float* centers = (const float*)d_in[1];   // (64,) fp32
    float* out           = (float*)d_out;           // (8,3,64) fp32

    hx_all<<<GRID, 256>>>(x, centers, out);
}

// round 17
// speedup vs baseline: 1.4848x; 1.0303x over previous
#include <cuda_runtime.h>
#include <cuda_bf16.h>

// SoftHistogram via fine-histogram factorization, SINGLE kernel, uniform grid:
//   out[ch][j] = normalize( sum_t counts[ch][t] * W[t][j] )
// W[t][j] = per-pixel-normalized Gaussian weight at x_t = t/TF (round-binning
// via the 2^23 magic-FMA trick, rows t = 0..TF inclusive).
//
// R16 vs R15 (17.4us best):
//  - phase reorder: histogram (DRAM stream) FIRST, table expf after -> input
//    streaming starts at t=0 instead of behind ~2us of MUFU work.
//  - TF 2048 -> 1024: halves table build, merge REDs, contraction traffic.
//    Error scaling measured ~2x per TF halving (1.8e-5 @4096, 3.56e-5 @2048)
//    -> predict ~0.7-1.4e-4, >=7x margin.

#define TF    1024
#define ROWS  (TF + 1)            // 1025 table rows (bin 0..1024)
#define RPAD  1028                // zeroed count range
#define SHW   2052                // smem words (fits 16x68 combine reuse)
#define NCH   24                  // 8 * 3 channels
#define BINS  64
#define PPC   (512 * 512)         // pixels per channel
#define HBLK  16                  // hist blocks per channel
#define PXB   (PPC / HBLK)        // 16384 pixels per hist block
#define GRID  (NCH * HBLK)        // 384 blocks
#define RSPL  65                  // contraction rows per block (16*65 >= 1025)

__device__ unsigned int g_counts[NCH][RPAD];  // fine histograms (BSS zero)
__device__ float        g_W[ROWS][BINS];      // weight table
__device__ float        g_hist[NCH][BINS];    // contraction accumulators (BSS zero)
__device__ unsigned int g_wdone;              // blocks done with table phase
__device__ unsigned int g_hdone[NCH];         // hist blocks completed per channel
__device__ unsigned int g_cdone[NCH];         // contraction blocks completed
__device__ unsigned int g_fin;                // channels fully finished

__global__ void __launch_bounds__(256) hx_all(const float* __restrict__ x,
                                              const float* __restrict__ centers,
                                              float* __restrict__ out) {
    __shared__ unsigned int sh[SHW];           // hist counts; reused as combine
    const int b    = blockIdx.x;               // 0..383
    const int tid  = threadIdx.x;
    const int warp = tid >> 5;
    const int lane = tid & 31;
    const int ch   = b / HBLK;
    const int blk  = b % HBLK;

    // ============ phase 0: per-channel-slice histogram (DRAM first!) ========
    for (int i = tid; i < RPAD; i += 256) sh[i] = 0u;
    __syncthreads();

    {
        const float4* __restrict__ p =
            reinterpret_cast<const float4*>(x + (size_t)ch * PPC + (size_t)blk * PXB);
        const float MAGIC = 8388608.0f;        // 2^23
#pragma unroll 4
        for (int i = 0; i < PXB / (256 * 4); i++) {
            float4 v = p[i * 256 + tid];
            unsigned b0 = __float_as_uint(fmaf(v.x, (float)TF, MAGIC)) & 0x7FFu;
            unsigned b1 = __float_as_uint(fmaf(v.y, (float)TF, MAGIC)) & 0x7FFu;
            unsigned b2 = __float_as_uint(fmaf(v.z, (float)TF, MAGIC)) & 0x7FFu;
            unsigned b3 = __float_as_uint(fmaf(v.w, (float)TF, MAGIC)) & 0x7FFu;
            atomicAdd(&sh[b0], 1u);
            atomicAdd(&sh[b1], 1u);
            atomicAdd(&sh[b2], 1u);
            atomicAdd(&sh[b3], 1u);
        }
    }
    __syncthreads();

    // ============ phase 1: merge counts to global ===========================
    {
        unsigned int* __restrict__ gc = g_counts[ch];
        for (int i = tid; i < ROWS; i += 256) {
            unsigned v = sh[i];
            if (v) atomicAdd(&gc[i], v);
        }
    }

    // ============ phase 2: W table (one row per warp, blocks 0..128) ========
    {
        const int t = b * 8 + warp;
        if (t < ROWS) {
            const float xt   = (float)t * (1.0f / (float)TF);
            const float invs = 1.0f / (0.02f + 1e-12f);   // reference SIGMA guard
            float z0 = (xt - __ldg(&centers[lane]))      * invs;
            float z1 = (xt - __ldg(&centers[lane + 32])) * invs;
            float e0 = expf(-0.5f * z0 * z0);
            float e1 = expf(-0.5f * z1 * z1);
            float s = e0 + e1;
#pragma unroll
            for (int off = 16; off > 0; off >>= 1)
                s += __shfl_xor_sync(0xffffffffu, s, off);
            const float r = 1.0f / (s + 1e-12f);
            g_W[t][lane]      = e0 * r;
            g_W[t][lane + 32] = e1 * r;
        }
    }

    // signal: counts merged + table slice written
    __threadfence();
    __syncthreads();
    if (tid == 0) {
        atomicAdd(&g_hdone[ch], 1u);
        atomicAdd(&g_wdone, 1u);
        while (*((volatile unsigned int*)&g_wdone) < (unsigned)GRID) __nanosleep(32);
        while (*((volatile unsigned int*)&g_hdone[ch]) < (unsigned)HBLK) __nanosleep(32);
        __threadfence();
    }
    __syncthreads();

    // ============ phase 3: contraction (transposed layout) ==================
    const int jg = tid & 15;                   // bin group (4 bins)
    const int rs = tid >> 4;                   // row slice 0..15
    const int r0 = blk * RSPL;
    const int r1 = min(r0 + RSPL, ROWS);

    float ax = 0.f, ay = 0.f, az = 0.f, aw = 0.f;
    const float4* __restrict__ W4 = reinterpret_cast<const float4*>(g_W);
    const unsigned int* __restrict__ gc = g_counts[ch];

    for (int r = r0 + rs; r < r1; r += 16) {
        float  c = (float)__ldcg(&gc[r]);      // L2 (written by other SMs)
        float4 w = __ldcg(&W4[r * 16 + jg]);
        ax = fmaf(c, w.x, ax);
        ay = fmaf(c, w.y, ay);
        az = fmaf(c, w.z, az);
        aw = fmaf(c, w.w, aw);
    }

    // all reads of this slice complete before anyone zeroes it (R8 race fix)
    __syncthreads();
    for (int r = r0 + tid; r < r1; r += 256) g_counts[ch][r] = 0u;

    float* __restrict__ part = reinterpret_cast<float*>(sh);   // reuse smem
    part[rs * (BINS + 4) + jg * 4 + 0] = ax;
    part[rs * (BINS + 4) + jg * 4 + 1] = ay;
    part[rs * (BINS + 4) + jg * 4 + 2] = az;
    part[rs * (BINS + 4) + jg * 4 + 3] = aw;
    __syncthreads();

    if (tid < BINS) {
        float s = 0.0f;
#pragma unroll
        for (int k = 0; k < 16; k++) s += part[k * (BINS + 4) + tid];
        atomicAdd(&g_hist[ch][tid], s);
    }
    __threadfence();
    __syncthreads();

    __shared__ unsigned int s_last;
    if (tid == 0)
        s_last = (atomicAdd(&g_cdone[ch], 1u) == HBLK - 1u) ? 1u : 0u;
    __syncthreads();
    if (!s_last) return;

    // ============ phase 4: last block per channel — normalize + reset =======
    __threadfence();

    float m = 0.0f;
    if (tid < BINS)
        m = *((volatile float*)&g_hist[ch][tid]) * (1.0f / (float)PPC);

    float t = (tid < BINS) ? m : 0.0f;
#pragma unroll
    for (int off = 16; off > 0; off >>= 1)
        t += __shfl_xor_sync(0xffffffffu, t, off);

    __shared__ float ws[8];
    if (lane == 0) ws[warp] = t;
    __syncthreads();

    if (tid < BINS) {
        float tot = ws[0] + ws[1];
        out[ch * BINS + tid] = m / (tot + 1e-12f);
        g_hist[ch][tid] = 0.0f;                // reset for next replay
    }
    if (tid == 0) {
        g_cdone[ch] = 0u;
        g_hdone[ch] = 0u;
        if (atomicAdd(&g_fin, 1u) == NCH - 1u) {   // globally last channel
            g_wdone = 0u;
            g_fin   = 0u;
        }
    }
}

// ---------------------------------------------------------------------------
extern "C" void kernel_launch(void* const* d_in, const int* in_sizes, int n_in,
                              void* d_out, int out_size) {
    const float* x       = (const float*)d_in[0];   // (8,3,512,512) fp32
    const float* centers = (const float*)d_in[1];   // (64,) fp32
    float* out           = (float*)d_out;           // (8,3,64) fp32

    hx_all<<<GRID, 256>>>(x, centers, out);
}